// round 1
// baseline (speedup 1.0000x reference)
#include <cuda_runtime.h>

#define A_DIM 256
#define B_DIM 256
#define V_DIM 12
#define D_DIM 512
#define C_DIM 8
#define H_DIM 256
#define VC    96
#define TEMP_INV 0.2f

// padded shared-memory strides (floats) for conflict-free access in k_tv
#define TSTR 522   // text row stride  (even, 522 % 32 = 10 -> distinct banks over a = l>>2)
#define VSTR 514   // video row stride (even, 514 % 32 = 2  -> distinct banks over v = l&3)

// ---------------- scratch (device globals; no dynamic allocation) ----------------
__device__ float g_vproj[B_DIM * V_DIM * C_DIM * H_DIM];   // 25.2 MB  [b][v][c][h]
__device__ float g_gram [B_DIM * C_DIM * V_DIM * V_DIM];   // 1.2 MB   [b][c][v][v']
__device__ float g_tproj[A_DIM * C_DIM * H_DIM];           // 2 MB     [a][c][h] (includes b1)
__device__ float g_tinv [A_DIM * C_DIM];                   // 1/||t_chunk||
__device__ float g_tv   [(size_t)B_DIM * A_DIM * VC];      // 25.2 MB  [b][a][v*8+c]

// ================= kernel 1: vproj[b,v,c,h] and gram[b,c,v,v'] =================
__global__ __launch_bounds__(256) void k_vproj(const float* __restrict__ video,
                                               const float* __restrict__ W1) {
    __shared__ float vid_s[V_DIM * D_DIM];  // 24 KB
    int b = blockIdx.x, tid = threadIdx.x;
    const float* vb = video + (size_t)b * V_DIM * D_DIM;
    for (int i = tid; i < V_DIM * D_DIM; i += 256) vid_s[i] = vb[i];

    // bottom half of W1 (video part), column h=tid, cached in registers
    float w1r[64];
#pragma unroll
    for (int w = 0; w < 64; ++w) w1r[w] = W1[(64 + w) * H_DIM + tid];
    __syncthreads();

    float* outb = g_vproj + (size_t)b * V_DIM * C_DIM * H_DIM;
    for (int v = 0; v < V_DIM; ++v) {
        for (int c = 0; c < C_DIM; ++c) {
            const float4* p = (const float4*)(vid_s + v * D_DIM + c * 64);
            float acc = 0.f;
#pragma unroll
            for (int q = 0; q < 16; ++q) {
                float4 x = p[q];   // uniform address -> smem broadcast
                acc = fmaf(x.x, w1r[4*q+0], acc);
                acc = fmaf(x.y, w1r[4*q+1], acc);
                acc = fmaf(x.z, w1r[4*q+2], acc);
                acc = fmaf(x.w, w1r[4*q+3], acc);
            }
            outb[(v * C_DIM + c) * H_DIM + tid] = acc;
        }
    }
    // gram (tiny: 1152 dots of length 64)
    float* gb = g_gram + b * C_DIM * V_DIM * V_DIM;
    for (int o = tid; o < C_DIM * V_DIM * V_DIM; o += 256) {
        int c  = o / (V_DIM * V_DIM);
        int r  = o % (V_DIM * V_DIM);
        int v1 = r / V_DIM, v2 = r % V_DIM;
        const float* p1 = vid_s + v1 * D_DIM + c * 64;
        const float* p2 = vid_s + v2 * D_DIM + c * 64;
        float acc = 0.f;
#pragma unroll
        for (int w = 0; w < 64; ++w) acc = fmaf(p1[w], p2[w], acc);
        gb[o] = acc;
    }
}

// ================= kernel 2: tproj[a,c,h] (+b1) and tinv[a,c] =================
__global__ __launch_bounds__(256) void k_tproj(const float* __restrict__ text,
                                               const float* __restrict__ W1,
                                               const float* __restrict__ b1) {
    __shared__ float t_s[D_DIM];
    int a = blockIdx.x, tid = threadIdx.x;
    for (int i = tid; i < D_DIM; i += 256) t_s[i] = text[(size_t)a * D_DIM + i];
    float w1r[64];
#pragma unroll
    for (int w = 0; w < 64; ++w) w1r[w] = W1[w * H_DIM + tid];  // top half (text part)
    float bias = b1[tid];
    __syncthreads();
    for (int c = 0; c < C_DIM; ++c) {
        const float4* p = (const float4*)(t_s + c * 64);
        float acc = bias;
#pragma unroll
        for (int q = 0; q < 16; ++q) {
            float4 x = p[q];
            acc = fmaf(x.x, w1r[4*q+0], acc);
            acc = fmaf(x.y, w1r[4*q+1], acc);
            acc = fmaf(x.z, w1r[4*q+2], acc);
            acc = fmaf(x.w, w1r[4*q+3], acc);
        }
        g_tproj[(a * C_DIM + c) * H_DIM + tid] = acc;
    }
    if (tid < C_DIM) {
        const float* p = t_s + tid * 64;
        float s = 0.f;
#pragma unroll
        for (int w = 0; w < 64; ++w) s = fmaf(p[w], p[w], s);
        g_tinv[a * C_DIM + tid] = rsqrtf(s);
    }
}

// ================= kernel 3: tv[b,a,vc] = t_chunk . video_chunk =================
// grid (B, 4): CTA = (b, tile of 64 a's). warp w handles c = w; thread:
//   a = (l>>2) + 8j  (j=0..7),  v = (l&3) + 4k (k=0..2)
__global__ __launch_bounds__(256) void k_tv(const float* __restrict__ text,
                                            const float* __restrict__ video) {
    extern __shared__ float sm[];
    float* t_s   = sm;               // 64 * TSTR floats
    float* vid_s = sm + 64 * TSTR;   // V_DIM * VSTR floats
    int b = blockIdx.x, at = blockIdx.y;
    int tid = threadIdx.x, warp = tid >> 5, l = tid & 31;

    for (int idx = tid; idx < 64 * D_DIM; idx += 256) {
        int a = idx >> 9, i = idx & 511;
        t_s[a * TSTR + i] = text[(size_t)(at * 64 + a) * D_DIM + i];
    }
    const float* vb = video + (size_t)b * V_DIM * D_DIM;
    for (int idx = tid; idx < V_DIM * D_DIM; idx += 256) {
        int v = idx >> 9, i = idx & 511;
        vid_s[v * VSTR + i] = vb[idx];
    }
    __syncthreads();

    int am = l >> 2, vm = l & 3, c = warp;
    float acc[8][3];
#pragma unroll
    for (int j = 0; j < 8; ++j)
#pragma unroll
        for (int k = 0; k < 3; ++k) acc[j][k] = 0.f;

    const float* tb = t_s   + c * 64;
    const float* vv = vid_s + c * 64;
    for (int i2 = 0; i2 < 32; ++i2) {
        float2 vr[3];
#pragma unroll
        for (int k = 0; k < 3; ++k)
            vr[k] = *(const float2*)(vv + (vm + 4 * k) * VSTR + 2 * i2);
#pragma unroll
        for (int j = 0; j < 8; ++j) {
            float2 tr = *(const float2*)(tb + (am + 8 * j) * TSTR + 2 * i2);
#pragma unroll
            for (int k = 0; k < 3; ++k) {
                acc[j][k] = fmaf(tr.x, vr[k].x, acc[j][k]);
                acc[j][k] = fmaf(tr.y, vr[k].y, acc[j][k]);
            }
        }
    }
#pragma unroll
    for (int j = 0; j < 8; ++j) {
        int ag = at * 64 + am + 8 * j;
#pragma unroll
        for (int k = 0; k < 3; ++k) {
            int vc = vm * 8 + warp + 32 * k;   // vc = v*8 + c
            g_tv[((size_t)b * A_DIM + ag) * VC + vc] = acc[j][k];
        }
    }
}

// ================= kernel 4: fused softmax + cosine + gating MLP =================
// CTA = b. smem holds vproj[b] (98KB) + gram[b] + W2. Each warp processes 4 a's
// per pass (8 passes). Lane layout for tv: vc = l + 32k -> c = l&7, v = (l>>3)+4k.
__global__ __launch_bounds__(256, 2) void k_main(const float* __restrict__ W2,
                                                 const float* __restrict__ b2p,
                                                 float* __restrict__ out) {
    extern __shared__ float sm[];
    float* vp_s   = sm;                                  // 24576
    float* gram_s = sm + V_DIM * C_DIM * H_DIM;          // 1152
    float* w2_s   = gram_s + C_DIM * V_DIM * V_DIM;      // 256
    int b = blockIdx.x, tid = threadIdx.x, warp = tid >> 5, l = tid & 31;

    const float* vpg = g_vproj + (size_t)b * V_DIM * C_DIM * H_DIM;
    for (int i = tid; i < V_DIM * C_DIM * H_DIM; i += 256) vp_s[i] = vpg[i];
    const float* gg = g_gram + b * C_DIM * V_DIM * V_DIM;
    for (int i = tid; i < C_DIM * V_DIM * V_DIM; i += 256) gram_s[i] = gg[i];
    for (int i = tid; i < H_DIM; i += 256) w2_s[i] = W2[i];
    float b2 = b2p[0];
    __syncthreads();

    const unsigned FULL = 0xffffffffu;
    int cmy = l & 7;    // this lane's c
    int vg  = l >> 3;   // this lane's v group

    for (int pass = 0; pass < 8; ++pass) {
        int a0 = pass * 32 + warp * 4;
        float wv[4][12];
        float cosr[4];
#pragma unroll
        for (int aq = 0; aq < 4; ++aq) {
            int a = a0 + aq;
            const float* tvp = g_tv + ((size_t)b * A_DIM + a) * VC;
            float t0 = __ldg(tvp + l);
            float t1 = __ldg(tvp + l + 32);
            float t2 = __ldg(tvp + l + 64);
            // logits[v] = sum over c (low 3 lane bits)
            float s0 = t0, s1 = t1, s2 = t2;
#pragma unroll
            for (int d = 1; d < 8; d <<= 1) {
                s0 += __shfl_xor_sync(FULL, s0, d);
                s1 += __shfl_xor_sync(FULL, s1, d);
                s2 += __shfl_xor_sync(FULL, s2, d);
            }
            // softmax over 12 v (3 regs x 4 lane-groups)
            float m = fmaxf(s0, fmaxf(s1, s2));
            m = fmaxf(m, __shfl_xor_sync(FULL, m, 8));
            m = fmaxf(m, __shfl_xor_sync(FULL, m, 16));
            float e0 = __expf((s0 - m) * TEMP_INV);
            float e1 = __expf((s1 - m) * TEMP_INV);
            float e2 = __expf((s2 - m) * TEMP_INV);
            float ssum = e0 + e1 + e2;
            ssum += __shfl_xor_sync(FULL, ssum, 8);
            ssum += __shfl_xor_sync(FULL, ssum, 16);
            float r = 1.0f / ssum;
            float w0 = e0 * r, w1 = e1 * r, w2v = e2 * r;  // own weights: v = vg, vg+4, vg+8
            // broadcast all 12 weights to every lane (constant indices only)
#pragma unroll
            for (int v = 0; v < 12; ++v) {
                float ev = (v < 4) ? w0 : ((v < 8) ? w1 : w2v);
                wv[aq][v] = __shfl_sync(FULL, ev, (v & 3) << 3);
            }
            // cosine numerator for c = l&7: sum_v w_v * tv[v,c]  (reduce over v groups)
            float cn = w0 * t0 + w1 * t1 + w2v * t2;
            cn += __shfl_xor_sync(FULL, cn, 8);
            cn += __shfl_xor_sync(FULL, cn, 16);
            // ||v_feat||^2 for c = l&7 via w^T G w (own v rows, reduce over v groups)
            float nv = 0.f;
#pragma unroll
            for (int k = 0; k < 3; ++k) {
                int v = vg + 4 * k;
                const float* gp = gram_s + cmy * (V_DIM * V_DIM) + v * V_DIM;
                float inner = 0.f;
#pragma unroll
                for (int v2 = 0; v2 < 12; ++v2) inner = fmaf(wv[aq][v2], gp[v2], inner);
                float wk = (k == 0) ? w0 : ((k == 1) ? w1 : w2v);
                nv = fmaf(wk, inner, nv);
            }
            nv += __shfl_xor_sync(FULL, nv, 8);
            nv += __shfl_xor_sync(FULL, nv, 16);
            cosr[aq] = cn * rsqrtf(nv) * __ldg(&g_tinv[a * C_DIM + cmy]);
        }

        // gating MLP: h = relu(tproj + sum_v w_v * vproj); weight = h.W2 + b2
        float outacc[4] = {0.f, 0.f, 0.f, 0.f};
        for (int c = 0; c < 8; ++c) {
            float wacc[4] = {0.f, 0.f, 0.f, 0.f};
            for (int j = 0; j < 8; ++j) {
                int h = l + (j << 5);
                float vp[12];
#pragma unroll
                for (int v = 0; v < 12; ++v) vp[v] = vp_s[(v * C_DIM + c) * H_DIM + h];
                float w2h = w2_s[h];
#pragma unroll
                for (int aq = 0; aq < 4; ++aq) {
                    float acc = __ldg(&g_tproj[((a0 + aq) * C_DIM + c) * H_DIM + h]);
#pragma unroll
                    for (int v = 0; v < 12; ++v) acc = fmaf(wv[aq][v], vp[v], acc);
                    acc = fmaxf(acc, 0.f);
                    wacc[aq] = fmaf(acc, w2h, wacc[aq]);
                }
            }
#pragma unroll
            for (int aq = 0; aq < 4; ++aq) {
                float s = wacc[aq];
#pragma unroll
                for (int d = 1; d < 32; d <<= 1) s += __shfl_xor_sync(FULL, s, d);
                float cc = __shfl_sync(FULL, cosr[aq], c);
                outacc[aq] = fmaf(cc, s + b2, outacc[aq]);
            }
        }
        if (l == 0) {
#pragma unroll
            for (int aq = 0; aq < 4; ++aq) out[(a0 + aq) * B_DIM + b] = outacc[aq];
        }
    }
}

// =================================== launch ===================================
extern "C" void kernel_launch(void* const* d_in, const int* in_sizes, int n_in,
                              void* d_out, int out_size) {
    (void)in_sizes; (void)n_in; (void)out_size;
    const float* text  = (const float*)d_in[0];
    const float* video = (const float*)d_in[1];
    const float* W1    = (const float*)d_in[2];
    const float* b1    = (const float*)d_in[3];
    const float* W2    = (const float*)d_in[4];
    const float* b2    = (const float*)d_in[5];
    float* out = (float*)d_out;

    int smem_tv   = (64 * TSTR + V_DIM * VSTR) * (int)sizeof(float);                      // 158,304 B
    int smem_main = (V_DIM * C_DIM * H_DIM + C_DIM * V_DIM * V_DIM + H_DIM)
                    * (int)sizeof(float);                                                 // 103,936 B
    cudaFuncSetAttribute(k_tv,   cudaFuncAttributeMaxDynamicSharedMemorySize, smem_tv);
    cudaFuncSetAttribute(k_main, cudaFuncAttributeMaxDynamicSharedMemorySize, smem_main);

    k_vproj<<<B_DIM, 256>>>(video, W1);
    k_tproj<<<A_DIM, 256>>>(text, W1, b1);
    k_tv<<<dim3(B_DIM, 4), 256, smem_tv>>>(text, video);
    k_main<<<B_DIM, 256, smem_main>>>(W2, b2, out);
}

// round 4
// speedup vs baseline: 1.0471x; 1.0471x over previous
#include <cuda_runtime.h>

#define A_DIM 256
#define B_DIM 256
#define V_DIM 12
#define D_DIM 512
#define C_DIM 8
#define H_DIM 256
#define VC    96
#define TEMP_INV 0.2f

// padded shared-memory strides (floats) for conflict-free access in k_tv
#define TSTR 522
#define VSTR 514

// ---------------- scratch (device globals; no dynamic allocation) ----------------
__device__ float g_vproj[B_DIM * V_DIM * C_DIM * H_DIM];   // 25.2 MB  [b][v][c][h]
__device__ float g_gram [B_DIM * C_DIM * V_DIM * V_DIM];   // 1.2 MB   [b][c][v][v']
__device__ float g_tproj[A_DIM * C_DIM * H_DIM];           // 2 MB     [a][c][h] (includes b1)
__device__ float g_tinv [A_DIM * C_DIM];                   // 1/||t_chunk||
__device__ float g_tv   [(size_t)B_DIM * A_DIM * VC];      // 25.2 MB  [b][a][v*8+c]
__device__ float g_wv   [(size_t)B_DIM * A_DIM * V_DIM];   // 3 MB     [b][a][v]
__device__ float g_cos  [(size_t)B_DIM * A_DIM * C_DIM];   // 2 MB     [b][a][c]

// ================= kernel 1: vproj[b,v,c,h] and gram[b,c,v,v'] =================
__global__ __launch_bounds__(256) void k_vproj(const float* __restrict__ video,
                                               const float* __restrict__ W1) {
    __shared__ float vid_s[V_DIM * D_DIM];  // 24 KB
    int b = blockIdx.x, tid = threadIdx.x;
    const float* vb = video + (size_t)b * V_DIM * D_DIM;
    for (int i = tid; i < V_DIM * D_DIM; i += 256) vid_s[i] = vb[i];

    float w1r[64];
#pragma unroll
    for (int w = 0; w < 64; ++w) w1r[w] = W1[(64 + w) * H_DIM + tid];
    __syncthreads();

    float* outb = g_vproj + (size_t)b * V_DIM * C_DIM * H_DIM;
    for (int v = 0; v < V_DIM; ++v) {
        for (int c = 0; c < C_DIM; ++c) {
            const float4* p = (const float4*)(vid_s + v * D_DIM + c * 64);
            float acc = 0.f;
#pragma unroll
            for (int q = 0; q < 16; ++q) {
                float4 x = p[q];
                acc = fmaf(x.x, w1r[4*q+0], acc);
                acc = fmaf(x.y, w1r[4*q+1], acc);
                acc = fmaf(x.z, w1r[4*q+2], acc);
                acc = fmaf(x.w, w1r[4*q+3], acc);
            }
            outb[(v * C_DIM + c) * H_DIM + tid] = acc;
        }
    }
    float* gb = g_gram + b * C_DIM * V_DIM * V_DIM;
    for (int o = tid; o < C_DIM * V_DIM * V_DIM; o += 256) {
        int c  = o / (V_DIM * V_DIM);
        int r  = o % (V_DIM * V_DIM);
        int v1 = r / V_DIM, v2 = r % V_DIM;
        const float* p1 = vid_s + v1 * D_DIM + c * 64;
        const float* p2 = vid_s + v2 * D_DIM + c * 64;
        float acc = 0.f;
#pragma unroll
        for (int w = 0; w < 64; ++w) acc = fmaf(p1[w], p2[w], acc);
        gb[o] = acc;
    }
}

// ================= kernel 2: tproj[a,c,h] (+b1) and tinv[a,c] =================
__global__ __launch_bounds__(256) void k_tproj(const float* __restrict__ text,
                                               const float* __restrict__ W1,
                                               const float* __restrict__ b1) {
    __shared__ float t_s[D_DIM];
    int a = blockIdx.x, tid = threadIdx.x;
    for (int i = tid; i < D_DIM; i += 256) t_s[i] = text[(size_t)a * D_DIM + i];
    float w1r[64];
#pragma unroll
    for (int w = 0; w < 64; ++w) w1r[w] = W1[w * H_DIM + tid];
    float bias = b1[tid];
    __syncthreads();
    for (int c = 0; c < C_DIM; ++c) {
        const float4* p = (const float4*)(t_s + c * 64);
        float acc = bias;
#pragma unroll
        for (int q = 0; q < 16; ++q) {
            float4 x = p[q];
            acc = fmaf(x.x, w1r[4*q+0], acc);
            acc = fmaf(x.y, w1r[4*q+1], acc);
            acc = fmaf(x.z, w1r[4*q+2], acc);
            acc = fmaf(x.w, w1r[4*q+3], acc);
        }
        g_tproj[(a * C_DIM + c) * H_DIM + tid] = acc;
    }
    if (tid < C_DIM) {
        const float* p = t_s + tid * 64;
        float s = 0.f;
#pragma unroll
        for (int w = 0; w < 64; ++w) s = fmaf(p[w], p[w], s);
        g_tinv[a * C_DIM + tid] = rsqrtf(s);
    }
}

// ================= kernel 3: tv[b,a,vc] = t_chunk . video_chunk =================
__global__ __launch_bounds__(256) void k_tv(const float* __restrict__ text,
                                            const float* __restrict__ video) {
    extern __shared__ float sm[];
    float* t_s   = sm;
    float* vid_s = sm + 64 * TSTR;
    int b = blockIdx.x, at = blockIdx.y;
    int tid = threadIdx.x, warp = tid >> 5, l = tid & 31;

    for (int idx = tid; idx < 64 * D_DIM; idx += 256) {
        int a = idx >> 9, i = idx & 511;
        t_s[a * TSTR + i] = text[(size_t)(at * 64 + a) * D_DIM + i];
    }
    const float* vb = video + (size_t)b * V_DIM * D_DIM;
    for (int idx = tid; idx < V_DIM * D_DIM; idx += 256) {
        int v = idx >> 9, i = idx & 511;
        vid_s[v * VSTR + i] = vb[idx];
    }
    __syncthreads();

    int am = l >> 2, vm = l & 3, c = warp;
    float acc[8][3];
#pragma unroll
    for (int j = 0; j < 8; ++j)
#pragma unroll
        for (int k = 0; k < 3; ++k) acc[j][k] = 0.f;

    const float* tb = t_s   + c * 64;
    const float* vv = vid_s + c * 64;
    for (int i2 = 0; i2 < 32; ++i2) {
        float2 vr[3];
#pragma unroll
        for (int k = 0; k < 3; ++k)
            vr[k] = *(const float2*)(vv + (vm + 4 * k) * VSTR + 2 * i2);
#pragma unroll
        for (int j = 0; j < 8; ++j) {
            float2 tr = *(const float2*)(tb + (am + 8 * j) * TSTR + 2 * i2);
#pragma unroll
            for (int k = 0; k < 3; ++k) {
                acc[j][k] = fmaf(tr.x, vr[k].x, acc[j][k]);
                acc[j][k] = fmaf(tr.y, vr[k].y, acc[j][k]);
            }
        }
    }
#pragma unroll
    for (int j = 0; j < 8; ++j) {
        int ag = at * 64 + am + 8 * j;
#pragma unroll
        for (int k = 0; k < 3; ++k) {
            int vc = vm * 8 + warp + 32 * k;
            g_tv[((size_t)b * A_DIM + ag) * VC + vc] = acc[j][k];
        }
    }
}

// ================= kernel 4: softmax + cosine, thread per (a,b), NO shuffles ====
// Writes g_wv[b][a][12], g_cos[b][a][8], and out[a][b] = b2 * sum_c cos.
__global__ __launch_bounds__(256) void k_soft(const float* __restrict__ b2p,
                                              float* __restrict__ out) {
    __shared__ float gram_s[C_DIM * V_DIM * V_DIM];   // 4.6 KB
    int b = blockIdx.x, a = threadIdx.x;
    const float* gg = g_gram + b * C_DIM * V_DIM * V_DIM;
    for (int i = a; i < C_DIM * V_DIM * V_DIM; i += 256) gram_s[i] = gg[i];
    __syncthreads();

    const float4* tvp = (const float4*)(g_tv + ((size_t)b * A_DIM + a) * VC);

    // pass 1: logits[v] = sum_c tv[v][c]
    float logit[12];
#pragma unroll
    for (int v = 0; v < 12; ++v) {
        float4 x0 = __ldg(tvp + 2 * v);
        float4 x1 = __ldg(tvp + 2 * v + 1);
        logit[v] = (x0.x + x0.y) + (x0.z + x0.w) + (x1.x + x1.y) + (x1.z + x1.w);
    }
    float m = logit[0];
#pragma unroll
    for (int v = 1; v < 12; ++v) m = fmaxf(m, logit[v]);
    float wv[12], ssum = 0.f;
#pragma unroll
    for (int v = 0; v < 12; ++v) { wv[v] = __expf((logit[v] - m) * TEMP_INV); ssum += wv[v]; }
    float rs = 1.0f / ssum;
#pragma unroll
    for (int v = 0; v < 12; ++v) wv[v] *= rs;

    // pass 2: cn[c] = sum_v wv[v] * tv[v][c]  (reload tv; L2-resident)
    float cn[8];
#pragma unroll
    for (int c = 0; c < 8; ++c) cn[c] = 0.f;
#pragma unroll
    for (int v = 0; v < 12; ++v) {
        float4 x0 = __ldg(tvp + 2 * v);
        float4 x1 = __ldg(tvp + 2 * v + 1);
        cn[0] = fmaf(wv[v], x0.x, cn[0]); cn[1] = fmaf(wv[v], x0.y, cn[1]);
        cn[2] = fmaf(wv[v], x0.z, cn[2]); cn[3] = fmaf(wv[v], x0.w, cn[3]);
        cn[4] = fmaf(wv[v], x1.x, cn[4]); cn[5] = fmaf(wv[v], x1.y, cn[5]);
        cn[6] = fmaf(wv[v], x1.z, cn[6]); cn[7] = fmaf(wv[v], x1.w, cn[7]);
    }

    // nv[c] = w^T G_c w ; cos[c] = cn * rsqrt(nv) * tinv
    float cosr[8], cossum = 0.f;
#pragma unroll
    for (int c = 0; c < 8; ++c) {
        const float* gp = gram_s + c * (V_DIM * V_DIM);
        float nv = 0.f;
#pragma unroll
        for (int v = 0; v < 12; ++v) {
            float inner = 0.f;
#pragma unroll
            for (int v2 = 0; v2 < 12; ++v2) inner = fmaf(wv[v2], gp[v * 12 + v2], inner);
            nv = fmaf(wv[v], inner, nv);
        }
        cosr[c] = cn[c] * rsqrtf(nv) * __ldg(&g_tinv[a * C_DIM + c]);
        cossum += cosr[c];
    }

    float4* wvo = (float4*)(g_wv + ((size_t)b * A_DIM + a) * V_DIM);
    wvo[0] = make_float4(wv[0], wv[1], wv[2], wv[3]);
    wvo[1] = make_float4(wv[4], wv[5], wv[6], wv[7]);
    wvo[2] = make_float4(wv[8], wv[9], wv[10], wv[11]);
    float4* cso = (float4*)(g_cos + ((size_t)b * A_DIM + a) * C_DIM);
    cso[0] = make_float4(cosr[0], cosr[1], cosr[2], cosr[3]);
    cso[1] = make_float4(cosr[4], cosr[5], cosr[6], cosr[7]);
    out[a * B_DIM + b] = __ldg(b2p) * cossum;   // init: b2 * sum_c cos
}

// ================= kernel 5: gating MLP, c-split, 3 CTAs/SM ====================
// grid (B, 2): CTA = (b, 4 centers). smem = 64KB exactly.
// Thread: hp = tid&127 (h-pair 2hp,2hp+1), grp = tid>>7 splits a.
__global__ __launch_bounds__(256, 3) void k_main(const float* __restrict__ W2,
                                                 float* __restrict__ out) {
    extern __shared__ float sm[];
    float* vp_s  = sm;                 // [v][cloc][h] : 12*4*256 = 12288 floats
    float* wv_s  = sm + 12288;         // [a][12]      : 3072 floats
    float* cos_s = sm + 15360;         // [a][cloc]    : 1024 floats
    int b = blockIdx.x, cs = blockIdx.y;
    int tid = threadIdx.x;

    // load vproj slice: c in [cs*4, cs*4+4)
    {
        const float4* src = (const float4*)g_vproj;
        float4* dst = (float4*)vp_s;
        for (int i = tid; i < 3072; i += 256) {
            int v = i >> 8, r = i & 255, cloc = r >> 6, h4 = r & 63;
            dst[i] = src[(((size_t)b * V_DIM + v) * C_DIM + cs * 4 + cloc) * 64 + h4];
        }
    }
    {
        const float4* src = (const float4*)(g_wv + (size_t)b * A_DIM * V_DIM);
        float4* dst = (float4*)wv_s;
        for (int i = tid; i < 768; i += 256) dst[i] = src[i];
    }
    {
        float4* dst = (float4*)cos_s;
        int a = tid;
        dst[a] = *(const float4*)(g_cos + ((size_t)b * A_DIM + a) * C_DIM + cs * 4);
    }
    __syncthreads();

    int hp = tid & 127, grp = tid >> 7;
    int lane = tid & 31;
    float2 w2p = __ldg((const float2*)W2 + hp);

    for (int ablk = 0; ablk < 32; ++ablk) {
        int a0 = grp * 128 + ablk * 4;
        float wv[4][12];
#pragma unroll
        for (int aq = 0; aq < 4; ++aq) {
            const float4* wp = (const float4*)(wv_s + (a0 + aq) * 12);
            float4 x = wp[0], y = wp[1], z = wp[2];
            wv[aq][0]=x.x; wv[aq][1]=x.y; wv[aq][2]=x.z; wv[aq][3]=x.w;
            wv[aq][4]=y.x; wv[aq][5]=y.y; wv[aq][6]=y.z; wv[aq][7]=y.w;
            wv[aq][8]=z.x; wv[aq][9]=z.y; wv[aq][10]=z.z; wv[aq][11]=z.w;
        }
        float outp[4] = {0.f, 0.f, 0.f, 0.f};
#pragma unroll
        for (int cloc = 0; cloc < 4; ++cloc) {
            float2 acc[4];
#pragma unroll
            for (int aq = 0; aq < 4; ++aq)
                acc[aq] = __ldg((const float2*)(g_tproj
                          + ((size_t)(a0 + aq) * C_DIM + cs * 4 + cloc) * H_DIM) + hp);
#pragma unroll
            for (int v = 0; v < 12; ++v) {
                float2 vp = *(const float2*)(vp_s + (v * 4 + cloc) * H_DIM + 2 * hp);
#pragma unroll
                for (int aq = 0; aq < 4; ++aq) {
                    acc[aq].x = fmaf(wv[aq][v], vp.x, acc[aq].x);
                    acc[aq].y = fmaf(wv[aq][v], vp.y, acc[aq].y);
                }
            }
#pragma unroll
            for (int aq = 0; aq < 4; ++aq) {
                float rx = fmaxf(acc[aq].x, 0.f);
                float ry = fmaxf(acc[aq].y, 0.f);
                float val = fmaf(rx, w2p.x, ry * w2p.y);
                float cc = cos_s[(a0 + aq) * 4 + cloc];   // uniform -> broadcast
                outp[aq] = fmaf(cc, val, outp[aq]);
            }
        }
        const unsigned FULL = 0xffffffffu;
#pragma unroll
        for (int aq = 0; aq < 4; ++aq) {
            float s = outp[aq];
#pragma unroll
            for (int d = 1; d < 32; d <<= 1) s += __shfl_xor_sync(FULL, s, d);
            if (lane == 0) atomicAdd(&out[(a0 + aq) * B_DIM + b], s);
        }
    }
}

// =================================== launch ===================================
extern "C" void kernel_launch(void* const* d_in, const int* in_sizes, int n_in,
                              void* d_out, int out_size) {
    (void)in_sizes; (void)n_in; (void)out_size;
    const float* text  = (const float*)d_in[0];
    const float* video = (const float*)d_in[1];
    const float* W1    = (const float*)d_in[2];
    const float* b1    = (const float*)d_in[3];
    const float* W2    = (const float*)d_in[4];
    const float* b2    = (const float*)d_in[5];
    float* out = (float*)d_out;

    int smem_tv   = (64 * TSTR + V_DIM * VSTR) * (int)sizeof(float);   // 158,304 B
    int smem_main = 16384 * (int)sizeof(float);                         // 65,536 B
    cudaFuncSetAttribute(k_tv,   cudaFuncAttributeMaxDynamicSharedMemorySize, smem_tv);
    cudaFuncSetAttribute(k_main, cudaFuncAttributeMaxDynamicSharedMemorySize, smem_main);

    k_vproj<<<B_DIM, 256>>>(video, W1);
    k_tproj<<<A_DIM, 256>>>(text, W1, b1);
    k_tv<<<dim3(B_DIM, 4), 256, smem_tv>>>(text, video);
    k_soft<<<B_DIM, 256>>>(b2, out);
    k_main<<<dim3(B_DIM, 2), 256, smem_main>>>(W2, out);
}

// round 7
// speedup vs baseline: 1.1148x; 1.0647x over previous
#include <cuda_runtime.h>

#define A_DIM 256
#define B_DIM 256
#define V_DIM 12
#define D_DIM 512
#define C_DIM 8
#define H_DIM 256
#define VC    96
#define TEMP_INV 0.2f

typedef unsigned long long ull;

// f32x2 packed math (FFMA2 — only reachable via PTX, ptxas never auto-fuses)
#define FMA_F32X2(d, a, b, c) \
    asm("fma.rn.f32x2 %0, %1, %2, %3;" : "=l"(d) : "l"(a), "l"(b), "l"(c))
#define PACK_F32X2(out, lo, hi) \
    asm("mov.b64 %0, {%1, %2};" : "=l"(out) : "f"(lo), "f"(hi))
#define UNPACK_F32X2(lo, hi, in) \
    asm("mov.b64 {%0, %1}, %2;" : "=f"(lo), "=f"(hi) : "l"(in))

// padded shared-memory strides (floats) for conflict-free access in k_tv
#define TSTR 522
#define VSTR 514

// ---------------- scratch (device globals; no dynamic allocation) ----------------
__device__ float g_vproj[B_DIM * V_DIM * C_DIM * H_DIM];   // 25.2 MB  [b][v][c][h]
__device__ float g_gram [B_DIM * C_DIM * V_DIM * V_DIM];   // 1.2 MB   [b][c][v][v']
__device__ float g_tproj[A_DIM * C_DIM * H_DIM];           // 2 MB     [a][c][h] (includes b1)
__device__ float g_tinv [A_DIM * C_DIM];                   // 1/||t_chunk||
__device__ float g_tv   [(size_t)B_DIM * A_DIM * VC];      // 25.2 MB  [b][a][v*8+c]
__device__ float g_wv   [(size_t)B_DIM * A_DIM * V_DIM];   // 3 MB     [b][a][v]
__device__ float g_cos  [(size_t)B_DIM * A_DIM * C_DIM];   // 2 MB     [b][a][c]

// ================= kernel 1: vproj[b,v,c,h] and gram[b,c,v,v'] =================
__global__ __launch_bounds__(256) void k_vproj(const float* __restrict__ video,
                                               const float* __restrict__ W1) {
    __shared__ float vid_s[V_DIM * D_DIM];  // 24 KB
    int b = blockIdx.x, tid = threadIdx.x;
    const float* vb = video + (size_t)b * V_DIM * D_DIM;
    for (int i = tid; i < V_DIM * D_DIM; i += 256) vid_s[i] = vb[i];

    float w1r[64];
#pragma unroll
    for (int w = 0; w < 64; ++w) w1r[w] = W1[(64 + w) * H_DIM + tid];
    __syncthreads();

    float* outb = g_vproj + (size_t)b * V_DIM * C_DIM * H_DIM;
    for (int v = 0; v < V_DIM; ++v) {
        for (int c = 0; c < C_DIM; ++c) {
            const float4* p = (const float4*)(vid_s + v * D_DIM + c * 64);
            float acc = 0.f;
#pragma unroll
            for (int q = 0; q < 16; ++q) {
                float4 x = p[q];
                acc = fmaf(x.x, w1r[4*q+0], acc);
                acc = fmaf(x.y, w1r[4*q+1], acc);
                acc = fmaf(x.z, w1r[4*q+2], acc);
                acc = fmaf(x.w, w1r[4*q+3], acc);
            }
            outb[(v * C_DIM + c) * H_DIM + tid] = acc;
        }
    }
    float* gb = g_gram + b * C_DIM * V_DIM * V_DIM;
    for (int o = tid; o < C_DIM * V_DIM * V_DIM; o += 256) {
        int c  = o / (V_DIM * V_DIM);
        int r  = o % (V_DIM * V_DIM);
        int v1 = r / V_DIM, v2 = r % V_DIM;
        const float* p1 = vid_s + v1 * D_DIM + c * 64;
        const float* p2 = vid_s + v2 * D_DIM + c * 64;
        float acc = 0.f;
#pragma unroll
        for (int w = 0; w < 64; ++w) acc = fmaf(p1[w], p2[w], acc);
        gb[o] = acc;
    }
}

// ================= kernel 2: tproj[a,c,h] (+b1) and tinv[a,c] =================
__global__ __launch_bounds__(256) void k_tproj(const float* __restrict__ text,
                                               const float* __restrict__ W1,
                                               const float* __restrict__ b1) {
    __shared__ float t_s[D_DIM];
    int a = blockIdx.x, tid = threadIdx.x;
    for (int i = tid; i < D_DIM; i += 256) t_s[i] = text[(size_t)a * D_DIM + i];
    float w1r[64];
#pragma unroll
    for (int w = 0; w < 64; ++w) w1r[w] = W1[w * H_DIM + tid];
    float bias = b1[tid];
    __syncthreads();
    for (int c = 0; c < C_DIM; ++c) {
        const float4* p = (const float4*)(t_s + c * 64);
        float acc = bias;
#pragma unroll
        for (int q = 0; q < 16; ++q) {
            float4 x = p[q];
            acc = fmaf(x.x, w1r[4*q+0], acc);
            acc = fmaf(x.y, w1r[4*q+1], acc);
            acc = fmaf(x.z, w1r[4*q+2], acc);
            acc = fmaf(x.w, w1r[4*q+3], acc);
        }
        g_tproj[(a * C_DIM + c) * H_DIM + tid] = acc;
    }
    if (tid < C_DIM) {
        const float* p = t_s + tid * 64;
        float s = 0.f;
#pragma unroll
        for (int w = 0; w < 64; ++w) s = fmaf(p[w], p[w], s);
        g_tinv[a * C_DIM + tid] = rsqrtf(s);
    }
}

// ================= kernel 3: tv[b,a,vc] = t_chunk . video_chunk =================
__global__ __launch_bounds__(256) void k_tv(const float* __restrict__ text,
                                            const float* __restrict__ video) {
    extern __shared__ float sm[];
    float* t_s   = sm;
    float* vid_s = sm + 64 * TSTR;
    int b = blockIdx.x, at = blockIdx.y;
    int tid = threadIdx.x, warp = tid >> 5, l = tid & 31;

    for (int idx = tid; idx < 64 * D_DIM; idx += 256) {
        int a = idx >> 9, i = idx & 511;
        t_s[a * TSTR + i] = text[(size_t)(at * 64 + a) * D_DIM + i];
    }
    const float* vb = video + (size_t)b * V_DIM * D_DIM;
    for (int idx = tid; idx < V_DIM * D_DIM; idx += 256) {
        int v = idx >> 9, i = idx & 511;
        vid_s[v * VSTR + i] = vb[idx];
    }
    __syncthreads();

    int am = l >> 2, vm = l & 3, c = warp;
    float acc[8][3];
#pragma unroll
    for (int j = 0; j < 8; ++j)
#pragma unroll
        for (int k = 0; k < 3; ++k) acc[j][k] = 0.f;

    const float* tb = t_s   + c * 64;
    const float* vv = vid_s + c * 64;
    for (int i2 = 0; i2 < 32; ++i2) {
        float2 vr[3];
#pragma unroll
        for (int k = 0; k < 3; ++k)
            vr[k] = *(const float2*)(vv + (vm + 4 * k) * VSTR + 2 * i2);
#pragma unroll
        for (int j = 0; j < 8; ++j) {
            float2 tr = *(const float2*)(tb + (am + 8 * j) * TSTR + 2 * i2);
#pragma unroll
            for (int k = 0; k < 3; ++k) {
                acc[j][k] = fmaf(tr.x, vr[k].x, acc[j][k]);
                acc[j][k] = fmaf(tr.y, vr[k].y, acc[j][k]);
            }
        }
    }
#pragma unroll
    for (int j = 0; j < 8; ++j) {
        int ag = at * 64 + am + 8 * j;
#pragma unroll
        for (int k = 0; k < 3; ++k) {
            int vc = vm * 8 + warp + 32 * k;
            g_tv[((size_t)b * A_DIM + ag) * VC + vc] = acc[j][k];
        }
    }
}

// ================= kernel 4: softmax + cosine, thread per (a,b), NO shuffles ====
// grid (B, 2) x 128 threads: a = blockIdx.y*128 + tid.
// Writes g_wv[b][a][12], g_cos[b][a][8], and out[a][b] = b2 * sum_c cos.
__global__ __launch_bounds__(128) void k_soft(const float* __restrict__ b2p,
                                              float* __restrict__ out) {
    __shared__ float gram_s[C_DIM * V_DIM * V_DIM];   // 4.6 KB
    int b = blockIdx.x, tid = threadIdx.x;
    int a = blockIdx.y * 128 + tid;
    const float* gg = g_gram + b * C_DIM * V_DIM * V_DIM;
    for (int i = tid; i < C_DIM * V_DIM * V_DIM; i += 128) gram_s[i] = gg[i];
    __syncthreads();

    const float4* tvp = (const float4*)(g_tv + ((size_t)b * A_DIM + a) * VC);

    // pass 1: logits[v] = sum_c tv[v][c]
    float logit[12];
#pragma unroll
    for (int v = 0; v < 12; ++v) {
        float4 x0 = __ldg(tvp + 2 * v);
        float4 x1 = __ldg(tvp + 2 * v + 1);
        logit[v] = (x0.x + x0.y) + (x0.z + x0.w) + (x1.x + x1.y) + (x1.z + x1.w);
    }
    float m = logit[0];
#pragma unroll
    for (int v = 1; v < 12; ++v) m = fmaxf(m, logit[v]);
    float wv[12], ssum = 0.f;
#pragma unroll
    for (int v = 0; v < 12; ++v) { wv[v] = __expf((logit[v] - m) * TEMP_INV); ssum += wv[v]; }
    float rs = 1.0f / ssum;
#pragma unroll
    for (int v = 0; v < 12; ++v) wv[v] *= rs;

    // pass 2: cn[c] = sum_v wv[v] * tv[v][c]  (reload tv; L1/L2-hot)
    float cn[8];
#pragma unroll
    for (int c = 0; c < 8; ++c) cn[c] = 0.f;
#pragma unroll
    for (int v = 0; v < 12; ++v) {
        float4 x0 = __ldg(tvp + 2 * v);
        float4 x1 = __ldg(tvp + 2 * v + 1);
        cn[0] = fmaf(wv[v], x0.x, cn[0]); cn[1] = fmaf(wv[v], x0.y, cn[1]);
        cn[2] = fmaf(wv[v], x0.z, cn[2]); cn[3] = fmaf(wv[v], x0.w, cn[3]);
        cn[4] = fmaf(wv[v], x1.x, cn[4]); cn[5] = fmaf(wv[v], x1.y, cn[5]);
        cn[6] = fmaf(wv[v], x1.z, cn[6]); cn[7] = fmaf(wv[v], x1.w, cn[7]);
    }

    // nv[c] = w^T G_c w ; cos[c] = cn * rsqrt(nv) * tinv
    float cosr[8], cossum = 0.f;
#pragma unroll
    for (int c = 0; c < 8; ++c) {
        const float* gp = gram_s + c * (V_DIM * V_DIM);
        float nv = 0.f;
#pragma unroll
        for (int v = 0; v < 12; ++v) {
            float inner = 0.f;
#pragma unroll
            for (int v2 = 0; v2 < 12; ++v2) inner = fmaf(wv[v2], gp[v * 12 + v2], inner);
            nv = fmaf(wv[v], inner, nv);
        }
        cosr[c] = cn[c] * rsqrtf(nv) * __ldg(&g_tinv[a * C_DIM + c]);
        cossum += cosr[c];
    }

    float4* wvo = (float4*)(g_wv + ((size_t)b * A_DIM + a) * V_DIM);
    wvo[0] = make_float4(wv[0], wv[1], wv[2], wv[3]);
    wvo[1] = make_float4(wv[4], wv[5], wv[6], wv[7]);
    wvo[2] = make_float4(wv[8], wv[9], wv[10], wv[11]);
    float4* cso = (float4*)(g_cos + ((size_t)b * A_DIM + a) * C_DIM);
    cso[0] = make_float4(cosr[0], cosr[1], cosr[2], cosr[3]);
    cso[1] = make_float4(cosr[4], cosr[5], cosr[6], cosr[7]);
    out[a * B_DIM + b] = __ldg(b2p) * cossum;   // init: b2 * sum_c cos
}

// ================= kernel 5: gating MLP, c-split, f32x2, 3 CTAs/SM =============
// grid (B, 2): CTA = (b, 4 centers). smem = 64KB. a-block = 2 (no spills: ~72 regs).
// Thread: hp = tid&127 (h-pair 2hp,2hp+1), grp = tid>>7 splits a.
__global__ __launch_bounds__(256, 3) void k_main(const float* __restrict__ W2,
                                                 float* __restrict__ out) {
    extern __shared__ float sm[];
    float* vp_s  = sm;                 // [v][cloc][h] : 12*4*256 = 12288 floats
    float* wv_s  = sm + 12288;         // [a][12]      : 3072 floats
    float* cos_s = sm + 15360;         // [a][cloc]    : 1024 floats
    int b = blockIdx.x, cs = blockIdx.y;
    int tid = threadIdx.x;

    // load vproj slice: c in [cs*4, cs*4+4)
    {
        const float4* src = (const float4*)g_vproj;
        float4* dst = (float4*)vp_s;
        for (int i = tid; i < 3072; i += 256) {
            int v = i >> 8, r = i & 255, cloc = r >> 6, h4 = r & 63;
            dst[i] = src[(((size_t)b * V_DIM + v) * C_DIM + cs * 4 + cloc) * 64 + h4];
        }
    }
    {
        const float4* src = (const float4*)(g_wv + (size_t)b * A_DIM * V_DIM);
        float4* dst = (float4*)wv_s;
        for (int i = tid; i < 768; i += 256) dst[i] = src[i];
    }
    {
        float4* dst = (float4*)cos_s;
        int a = tid;
        dst[a] = *(const float4*)(g_cos + ((size_t)b * A_DIM + a) * C_DIM + cs * 4);
    }
    __syncthreads();

    int hp = tid & 127, grp = tid >> 7;
    int lane = tid & 31;
    float2 w2p = __ldg((const float2*)W2 + hp);
    const unsigned FULL = 0xffffffffu;

    for (int ablk = 0; ablk < 64; ++ablk) {
        int a0 = grp * 128 + ablk * 2;
        // pack softmax weights as (w,w) pairs for f32x2 (warp-uniform LDS broadcast)
        ull wvp[2][12];
#pragma unroll
        for (int aq = 0; aq < 2; ++aq)
#pragma unroll
            for (int v = 0; v < 12; ++v) {
                float w = wv_s[(a0 + aq) * 12 + v];
                PACK_F32X2(wvp[aq][v], w, w);
            }
        float outp0 = 0.f, outp1 = 0.f;
#pragma unroll
        for (int cloc = 0; cloc < 4; ++cloc) {
            // acc init = tproj pair (L2-resident LDG.64)
            float2 t0 = __ldg((const float2*)(g_tproj
                        + ((size_t)(a0 + 0) * C_DIM + cs * 4 + cloc) * H_DIM) + hp);
            float2 t1 = __ldg((const float2*)(g_tproj
                        + ((size_t)(a0 + 1) * C_DIM + cs * 4 + cloc) * H_DIM) + hp);
            ull acc0, acc1;
            PACK_F32X2(acc0, t0.x, t0.y);
            PACK_F32X2(acc1, t1.x, t1.y);
            const ull* vpp = (const ull*)(vp_s + cloc * H_DIM) + hp;
#pragma unroll
            for (int v = 0; v < 12; ++v) {
                ull vp = vpp[v * 4 * (H_DIM / 2)];   // (v*4+cloc)*H_DIM floats
                FMA_F32X2(acc0, vp, wvp[0][v], acc0);
                FMA_F32X2(acc1, vp, wvp[1][v], acc1);
            }
            float x0, y0, x1, y1;
            UNPACK_F32X2(x0, y0, acc0);
            UNPACK_F32X2(x1, y1, acc1);
            float val0 = fmaf(fmaxf(x0, 0.f), w2p.x, fmaxf(y0, 0.f) * w2p.y);
            float val1 = fmaf(fmaxf(x1, 0.f), w2p.x, fmaxf(y1, 0.f) * w2p.y);
            outp0 = fmaf(cos_s[(a0 + 0) * 4 + cloc], val0, outp0);
            outp1 = fmaf(cos_s[(a0 + 1) * 4 + cloc], val1, outp1);
        }
#pragma unroll
        for (int d = 1; d < 32; d <<= 1) {
            outp0 += __shfl_xor_sync(FULL, outp0, d);
            outp1 += __shfl_xor_sync(FULL, outp1, d);
        }
        if (lane == 0) {
            atomicAdd(&out[(a0 + 0) * B_DIM + b], outp0);
            atomicAdd(&out[(a0 + 1) * B_DIM + b], outp1);
        }
    }
}

// =================================== launch ===================================
extern "C" void kernel_launch(void* const* d_in, const int* in_sizes, int n_in,
                              void* d_out, int out_size) {
    (void)in_sizes; (void)n_in; (void)out_size;
    const float* text  = (const float*)d_in[0];
    const float* video = (const float*)d_in[1];
    const float* W1    = (const float*)d_in[2];
    const float* b1    = (const float*)d_in[3];
    const float* W2    = (const float*)d_in[4];
    const float* b2    = (const float*)d_in[5];
    float* out = (float*)d_out;

    int smem_tv   = (64 * TSTR + V_DIM * VSTR) * (int)sizeof(float);   // 158,304 B
    int smem_main = 16384 * (int)sizeof(float);                         // 65,536 B
    cudaFuncSetAttribute(k_tv,   cudaFuncAttributeMaxDynamicSharedMemorySize, smem_tv);
    cudaFuncSetAttribute(k_main, cudaFuncAttributeMaxDynamicSharedMemorySize, smem_main);

    k_vproj<<<B_DIM, 256>>>(video, W1);
    k_tproj<<<A_DIM, 256>>>(text, W1, b1);
    k_tv<<<dim3(B_DIM, 4), 256, smem_tv>>>(text, video);
    k_soft<<<dim3(B_DIM, 2), 128>>>(b2, out);
    k_main<<<dim3(B_DIM, 2), 256, smem_main>>>(W2, out);
}